// round 15
// baseline (speedup 1.0000x reference)
#include <cuda_runtime.h>
#include <cuda_bf16.h>
#include <cuda_fp16.h>
#include <cstdint>

#define N_NODES 100000
#define N_EDGES 640000
#define D 128
#define NB_SCAN ((N_NODES + 1023) / 1024)    // 98

#define CVT_BLOCKS 12500                     // N_NODES*D/4 / 256
#define HIST_BLOCKS 625                      // N_EDGES / (256*4)
#define WPREP_BLOCKS 513

// ---------------- scratch (device globals: zero at module load) ------------
__device__ __align__(16) __half g_pa16[N_NODES * D];
__device__ __align__(16) __half g_pb16[N_NODES * D];
// node tensors: fp16 [N][128]
__device__ __align__(16) __half g_x[N_NODES * D];
__device__ __align__(16) __half g_m[N_NODES * D];
__device__ __align__(16) __half g_h1[N_NODES * D];
__device__ __align__(16) __half g_h2[N_NODES * D];
// packed weights [K][N] fp16:
// rows [Ws1|Wn1 (0-255) | Ws2|Wn2 (256-511) | comp_pa (512-767) | comp_pb (768-1023)]
__device__ __align__(16) __half g_wh[1024 * D];
__device__ float g_bc[2 * D];                // composed predictor biases
// CSR  (INVARIANT: g_cnt == 0 and g_ready == 0 at kernel_launch entry;
//       k_edge restores this at the end of every launch)
// g_csr holds BYTE offsets (src_node * 256) for direct addressing in k_agg.
__device__ int g_cnt[N_NODES];
__device__ int g_rowptr[N_NODES + 1];
__device__ int g_csr[N_EDGES];
__device__ int g_bsum[NB_SCAN];
__device__ int g_ready[NB_SCAN];

// ---------------- fused prologue: x-cvt + dst-hist + weight prep -----------
__global__ void k_prep(const float* __restrict__ x, __half* __restrict__ xo,
                       const int* __restrict__ dst,
                       const float* __restrict__ Ws1, const float* __restrict__ Wn1,
                       const float* __restrict__ Ws2, const float* __restrict__ Wn2,
                       const float* __restrict__ Ws3, const float* __restrict__ Wn3,
                       const float* __restrict__ Wp1, const float* __restrict__ b3,
                       const float* __restrict__ bp1) {
    int blk = blockIdx.x, tid = threadIdx.x;
    if (blk < CVT_BLOCKS) {                       // ---- x fp32 -> fp16
        int i = blk * 256 + tid;                  // < 3.2M exactly
        float4 v = ((const float4*)x)[i];
        __half2* p = (__half2*)&xo[i * 4];
        p[0] = __floats2half2_rn(v.x, v.y);
        p[1] = __floats2half2_rn(v.z, v.w);
    } else if (blk < CVT_BLOCKS + HIST_BLOCKS) {  // ---- degree histogram x4
        int e4 = (blk - CVT_BLOCKS) * 256 + tid;  // < 160000 exactly
        int4 d4 = ((const int4*)dst)[e4];
        atomicAdd(&g_cnt[d4.x], 1);
        atomicAdd(&g_cnt[d4.y], 1);
        atomicAdd(&g_cnt[d4.z], 1);
        atomicAdd(&g_cnt[d4.w], 1);
    } else {                                      // ---- weight prep
        int wb = blk - CVT_BLOCKS - HIST_BLOCKS;  // 0..512
        if (wb < 256) {                           // layer 1/2 weights
            int i = wb * 256 + tid;
            int row = i >> 7, col = i & 127;
            const float* s; int lr;
            if      (row < 128)  { s = Ws1; lr = row; }
            else if (row < 256)  { s = Wn1; lr = row - 128; }
            else if (row < 384)  { s = Ws2; lr = row - 256; }
            else                 { s = Wn2; lr = row - 384; }
            g_wh[i] = __float2half_rn(s[lr * D + col]);
        } else if (wb < 512) {                    // composed predictor weights
            __shared__ float xr[2][128];
            int idx = (wb - 256) * 2 + (tid >> 7);
            int p = idx >> 7, i = idx & 127;
            int sub = tid >> 7, n = tid & 127;
            const float* X = (p & 1) ? Wn3 : Ws3;
            const float* Y = Wp1 + ((p >> 1) ? 128 * D : 0);
            xr[sub][n] = X[i * D + n];
            __syncthreads();
            float s = 0.f;
            #pragma unroll 8
            for (int k = 0; k < 128; k++) s += xr[sub][k] * Y[k * D + n];
            int dstrow = ((p < 2) ? 512 : 768) + (p & 1) * 128 + i;
            g_wh[dstrow * D + n] = __float2half_rn(s);
        } else {                                  // composed biases
            int half = tid >> 7, n = tid & 127;
            float s = (half == 0) ? bp1[n] : 0.f;
            for (int j = 0; j < 128; j++) s += b3[j] * Wp1[(half * 128 + j) * D + n];
            g_bc[half * D + n] = s;
        }
    }
}

// fused scan: per-block scan + decoupled aggregate lookback + rowptr + cnt reset
__global__ void k_scan_fused() {
    __shared__ int sh[1024];
    __shared__ int red[32];
    int tid = threadIdx.x, blk = blockIdx.x;
    int i = blk * 1024 + tid;
    int v = (i < N_NODES) ? g_cnt[i] : 0;
    sh[tid] = v;
    __syncthreads();
    for (int o = 1; o < 1024; o <<= 1) {
        int t = (tid >= o) ? sh[tid - o] : 0;
        __syncthreads();
        sh[tid] += t;
        __syncthreads();
    }
    int total = sh[1023];
    if (tid == 0) {
        *(volatile int*)&g_bsum[blk] = total;
        __threadfence();
        *(volatile int*)&g_ready[blk] = 1;
    }
    int myv = 0;
    for (int j = tid; j < blk; j += 1024) {
        while (*(volatile int*)&g_ready[j] == 0) {}
        myv += *(volatile int*)&g_bsum[j];
    }
    #pragma unroll
    for (int o = 16; o > 0; o >>= 1) myv += __shfl_xor_sync(0xffffffffu, myv, o);
    if ((tid & 31) == 0) red[tid >> 5] = myv;
    __syncthreads();
    if (tid == 0) {
        int s = 0;
        #pragma unroll
        for (int w = 0; w < 32; w++) s += red[w];
        red[0] = s;
    }
    __syncthreads();
    int pref = red[0];
    if (i < N_NODES) {
        g_rowptr[i] = pref + sh[tid] - v;    // global exclusive
        g_cnt[i] = 0;                        // reset for k_place
    }
    if (blk == NB_SCAN - 1 && tid == 1023) g_rowptr[N_NODES] = pref + total;
}

// 4 edges per thread; csr stores BYTE offsets (src * 256)
__global__ void k_place(const int* __restrict__ src, const int* __restrict__ dst) {
    int e4 = blockIdx.x * blockDim.x + threadIdx.x;
    if (e4 >= N_EDGES / 4) return;
    int4 d4 = ((const int4*)dst)[e4];
    int4 s4 = ((const int4*)src)[e4];
    int p0 = g_rowptr[d4.x] + atomicAdd(&g_cnt[d4.x], 1);
    int p1 = g_rowptr[d4.y] + atomicAdd(&g_cnt[d4.y], 1);
    int p2 = g_rowptr[d4.z] + atomicAdd(&g_cnt[d4.z], 1);
    int p3 = g_rowptr[d4.w] + atomicAdd(&g_cnt[d4.w], 1);
    g_csr[p0] = s4.x << 8; g_csr[p1] = s4.y << 8;
    g_csr[p2] = s4.z << 8; g_csr[p3] = s4.w << 8;
}

// ---------------- mean aggregation: half-warp/node, 4-edge fp16 tree -------
__global__ void k_agg(const __half* __restrict__ xin) {
    int g = blockIdx.x * blockDim.x + threadIdx.x;
    int node = g >> 4, lane16 = g & 15;
    if (node >= N_NODES) return;
    int beg = g_rowptr[node], end = g_rowptr[node + 1];
    const char* bp = (const char*)xin + lane16 * 16;
    float a0 = 0.f, a1 = 0.f, a2 = 0.f, a3 = 0.f;
    float a4 = 0.f, a5 = 0.f, a6 = 0.f, a7 = 0.f;
    int e = beg;
    for (; e + 3 < end; e += 4) {
        int o0 = g_csr[e], o1 = g_csr[e + 1], o2 = g_csr[e + 2], o3 = g_csr[e + 3];
        const uint4 v0 = *(const uint4*)(bp + o0);
        const uint4 v1 = *(const uint4*)(bp + o1);
        const uint4 v2 = *(const uint4*)(bp + o2);
        const uint4 v3 = *(const uint4*)(bp + o3);
        __half2 t0 = __hadd2(__hadd2(*(__half2*)&v0.x, *(__half2*)&v1.x),
                             __hadd2(*(__half2*)&v2.x, *(__half2*)&v3.x));
        __half2 t1 = __hadd2(__hadd2(*(__half2*)&v0.y, *(__half2*)&v1.y),
                             __hadd2(*(__half2*)&v2.y, *(__half2*)&v3.y));
        __half2 t2 = __hadd2(__hadd2(*(__half2*)&v0.z, *(__half2*)&v1.z),
                             __hadd2(*(__half2*)&v2.z, *(__half2*)&v3.z));
        __half2 t3 = __hadd2(__hadd2(*(__half2*)&v0.w, *(__half2*)&v1.w),
                             __hadd2(*(__half2*)&v2.w, *(__half2*)&v3.w));
        float2 f;
        f = __half22float2(t0); a0 += f.x; a1 += f.y;
        f = __half22float2(t1); a2 += f.x; a3 += f.y;
        f = __half22float2(t2); a4 += f.x; a5 += f.y;
        f = __half22float2(t3); a6 += f.x; a7 += f.y;
    }
    if (e + 1 < end) {
        int o0 = g_csr[e], o1 = g_csr[e + 1];
        e += 2;
        const uint4 v0 = *(const uint4*)(bp + o0);
        const uint4 v1 = *(const uint4*)(bp + o1);
        __half2 t0 = __hadd2(*(__half2*)&v0.x, *(__half2*)&v1.x);
        __half2 t1 = __hadd2(*(__half2*)&v0.y, *(__half2*)&v1.y);
        __half2 t2 = __hadd2(*(__half2*)&v0.z, *(__half2*)&v1.z);
        __half2 t3 = __hadd2(*(__half2*)&v0.w, *(__half2*)&v1.w);
        float2 f;
        f = __half22float2(t0); a0 += f.x; a1 += f.y;
        f = __half22float2(t1); a2 += f.x; a3 += f.y;
        f = __half22float2(t2); a4 += f.x; a5 += f.y;
        f = __half22float2(t3); a6 += f.x; a7 += f.y;
    }
    if (e < end) {
        const uint4 v = *(const uint4*)(bp + g_csr[e]);
        float2 f;
        f = __half22float2(*(__half2*)&v.x); a0 += f.x; a1 += f.y;
        f = __half22float2(*(__half2*)&v.y); a2 += f.x; a3 += f.y;
        f = __half22float2(*(__half2*)&v.z); a4 += f.x; a5 += f.y;
        f = __half22float2(*(__half2*)&v.w); a6 += f.x; a7 += f.y;
    }
    int deg = end - beg;
    float inv = 1.0f / (float)(deg > 1 ? deg : 1);
    uint4 outv;
    *(__half2*)&outv.x = __floats2half2_rn(a0 * inv, a1 * inv);
    *(__half2*)&outv.y = __floats2half2_rn(a2 * inv, a3 * inv);
    *(__half2*)&outv.z = __floats2half2_rn(a4 * inv, a5 * inv);
    *(__half2*)&outv.w = __floats2half2_rn(a6 * inv, a7 * inv);
    *(uint4*)((char*)g_m + (size_t)node * 256 + lane16 * 16) = outv;
}

// ---------------- tensor-core GEMM (fp16, 1-term, 3-stage, 2 CTA/SM) -------
__device__ __forceinline__ void ldsm4(uint32_t& r0, uint32_t& r1, uint32_t& r2,
                                      uint32_t& r3, uint32_t addr) {
    asm volatile("ldmatrix.sync.aligned.m8n8.x4.shared.b16 {%0,%1,%2,%3}, [%4];"
                 : "=r"(r0), "=r"(r1), "=r"(r2), "=r"(r3) : "r"(addr));
}
__device__ __forceinline__ void ldsm4t(uint32_t& r0, uint32_t& r1, uint32_t& r2,
                                       uint32_t& r3, uint32_t addr) {
    asm volatile("ldmatrix.sync.aligned.m8n8.x4.trans.shared.b16 {%0,%1,%2,%3}, [%4];"
                 : "=r"(r0), "=r"(r1), "=r"(r2), "=r"(r3) : "r"(addr));
}
__device__ __forceinline__ void mma_fp16(float* c, const uint32_t* a, const uint32_t* b) {
    asm volatile(
        "mma.sync.aligned.m16n8k16.row.col.f32.f16.f16.f32 "
        "{%0,%1,%2,%3},{%4,%5,%6,%7},{%8,%9},{%0,%1,%2,%3};"
        : "+f"(c[0]), "+f"(c[1]), "+f"(c[2]), "+f"(c[3])
        : "r"(a[0]), "r"(a[1]), "r"(a[2]), "r"(a[3]), "r"(b[0]), "r"(b[1]));
}
__device__ __forceinline__ void cp16(uint32_t s, const void* g, bool p) {
    asm volatile("cp.async.cg.shared.global [%0], [%1], 16, %2;"
                 :: "r"(s), "l"(g), "r"(p ? 16 : 0));
}

#define A_STRIDE 80u
#define B_STRIDE 272u
#define A_BYTES (128u * A_STRIDE)            // 10240
#define B_BYTES (32u * B_STRIDE)             // 8704
#define STAGE (A_BYTES + B_BYTES)            // 18944
#define GEMM_SMEM (3 * STAGE)                // 56832 -> 2 CTAs/SM

// out[M,128] = (A1|A2)[M,K=256] @ W[K,128] + bias ; fp16.
// If pred (gridDim.y==2): y==1 selects W+256 rows, bias+128, out=outB.
__global__ __launch_bounds__(256, 2) void k_gemm_tc(
    const __half* __restrict__ A1, const __half* __restrict__ A2,
    const __half* __restrict__ Wh,
    const float* __restrict__ bias,
    __half* __restrict__ outA, __half* __restrict__ outB,
    int M, int K)
{
    extern __shared__ char smdyn[];
    uint32_t base = (uint32_t)__cvta_generic_to_shared(smdyn);

    __half* outp = outA;
    if (outB && blockIdx.y == 1) {
        Wh += 256 * D; bias += 128; outp = outB;
    }

    int tid = threadIdx.x;
    int wid = tid >> 5, lane = tid & 31;
    int warp_m = (wid >> 2) * 64;
    int warp_n = (wid & 3) * 32;
    int m0 = blockIdx.x * 128;
    int nch = K / 32;

    float c[4][4][4];
    #pragma unroll
    for (int i = 0; i < 4; i++)
        #pragma unroll
        for (int j = 0; j < 4; j++)
            #pragma unroll
            for (int q = 0; q < 4; q++) c[i][j][q] = 0.f;

    auto load_chunk = [&](int ch) {
        uint32_t st = base + (uint32_t)(ch % 3) * STAGE;
        int kb = ch * 32;
        const __half* A = (kb < 128) ? A1 : A2;
        int ac = kb & 127;
        #pragma unroll
        for (int l = tid; l < 512; l += 256) {      // A: 128 rows x 4 segs(16B)
            int r = l >> 2, seg = l & 3;
            uint32_t so = (uint32_t)r * A_STRIDE + (uint32_t)seg * 16u;
            bool p = (m0 + r) < M;
            int rr = p ? (m0 + r) : 0;
            cp16(st + so, A + (size_t)rr * D + ac + seg * 8, p);
        }
        #pragma unroll
        for (int l = tid; l < 512; l += 256) {      // B: 32 rows x 16 segs
            int r = l >> 4, seg = l & 15;
            uint32_t so = (uint32_t)r * B_STRIDE + (uint32_t)seg * 16u;
            cp16(st + A_BYTES + so, Wh + (size_t)(kb + r) * D + seg * 8, true);
        }
        asm volatile("cp.async.commit_group;" ::: "memory");
    };

    load_chunk(0);
    load_chunk(1);

    int lr = (lane & 7) + 8 * ((lane >> 3) & 1);
    int lc = 8 * (lane >> 4);

    for (int ch = 0; ch < nch; ch++) {
        if (ch + 1 < nch) {
            asm volatile("cp.async.wait_group 1;" ::: "memory");
        } else {
            asm volatile("cp.async.wait_group 0;" ::: "memory");
        }
        __syncthreads();     // single barrier: orders stage reuse + visibility
        if (ch + 2 < nch) load_chunk(ch + 2);

        uint32_t st  = base + (uint32_t)(ch % 3) * STAGE;
        uint32_t a_b = st;
        uint32_t b_b = st + A_BYTES;

        #pragma unroll
        for (int ks = 0; ks < 2; ks++) {
            int k0 = ks * 16;
            uint32_t a[4][4];
            #pragma unroll
            for (int mi = 0; mi < 4; mi++) {
                uint32_t ro = (uint32_t)(warp_m + mi * 16 + lr) * A_STRIDE
                            + (uint32_t)(k0 + lc) * 2u;
                ldsm4(a[mi][0], a[mi][1], a[mi][2], a[mi][3], a_b + ro);
            }
            uint32_t b[4][2];
            #pragma unroll
            for (int njp = 0; njp < 2; njp++) {
                uint32_t ro = (uint32_t)(k0 + lr) * B_STRIDE
                            + (uint32_t)(warp_n + njp * 16 + lc) * 2u;
                uint32_t r0, r1, r2, r3;
                ldsm4t(r0, r1, r2, r3, b_b + ro);
                b[2 * njp][0] = r0;     b[2 * njp][1] = r1;
                b[2 * njp + 1][0] = r2; b[2 * njp + 1][1] = r3;
            }
            #pragma unroll
            for (int mi = 0; mi < 4; mi++)
                #pragma unroll
                for (int nj = 0; nj < 4; nj++)
                    mma_fp16(c[mi][nj], a[mi], b[nj]);
        }
    }

    // epilogue: fp16 output
    #pragma unroll
    for (int mi = 0; mi < 4; mi++) {
        #pragma unroll
        for (int nj = 0; nj < 4; nj++) {
            int row0 = m0 + warp_m + mi * 16 + (lane >> 2);
            int col  = warp_n + nj * 8 + (lane & 3) * 2;
            float b0 = bias ? bias[col] : 0.f;
            float b1 = bias ? bias[col + 1] : 0.f;
            #pragma unroll
            for (int h = 0; h < 2; h++) {
                int row = row0 + 8 * h;
                if (row < M) {
                    float v0 = c[mi][nj][2 * h]     + b0;
                    float v1 = c[mi][nj][2 * h + 1] + b1;
                    *(__half2*)&outp[(size_t)row * D + col] =
                        __floats2half2_rn(v0, v1);
                }
            }
        }
    }
}

// ---------------- edge scoring + state reset (16 lanes/edge) ----------------
__global__ void k_edge(const int* __restrict__ s1, const int* __restrict__ d1,
                       const int* __restrict__ s2, const int* __restrict__ d2,
                       const float* __restrict__ Wp2, const float* __restrict__ bp2,
                       float* __restrict__ out)
{
    int g = blockIdx.x * blockDim.x + threadIdx.x;
    // restore launch-entry invariant (g_cnt == 0, g_ready == 0)
    if (g < N_NODES) g_cnt[g] = 0;
    if (g < NB_SCAN) g_ready[g] = 0;
    int e = g >> 4, lane16 = g & 15;
    if (e >= 2 * N_EDGES) return;
    int ss, dd;
    if (e < N_EDGES) { ss = s1[e]; dd = d1[e]; }
    else             { ss = s2[e - N_EDGES]; dd = d2[e - N_EDGES]; }

    const char* pab = (const char*)g_pa16 + ((size_t)ss << 8) + lane16 * 16;
    const char* pbb = (const char*)g_pb16 + ((size_t)dd << 8) + lane16 * 16;
    uint4 av = *(const uint4*)pab;
    uint4 bv = *(const uint4*)pbb;
    float4 w0 = *(const float4*)&Wp2[lane16 * 8];
    float4 w1 = *(const float4*)&Wp2[lane16 * 8 + 4];

    float2 a0 = __half22float2(*(__half2*)&av.x);
    float2 a1 = __half22float2(*(__half2*)&av.y);
    float2 a2 = __half22float2(*(__half2*)&av.z);
    float2 a3 = __half22float2(*(__half2*)&av.w);
    float2 b0 = __half22float2(*(__half2*)&bv.x);
    float2 b1 = __half22float2(*(__half2*)&bv.y);
    float2 b2 = __half22float2(*(__half2*)&bv.z);
    float2 b3 = __half22float2(*(__half2*)&bv.w);

    float p = fmaxf(a0.x + b0.x, 0.f) * w0.x
            + fmaxf(a0.y + b0.y, 0.f) * w0.y
            + fmaxf(a1.x + b1.x, 0.f) * w0.z
            + fmaxf(a1.y + b1.y, 0.f) * w0.w
            + fmaxf(a2.x + b2.x, 0.f) * w1.x
            + fmaxf(a2.y + b2.y, 0.f) * w1.y
            + fmaxf(a3.x + b3.x, 0.f) * w1.z
            + fmaxf(a3.y + b3.y, 0.f) * w1.w;
    #pragma unroll
    for (int o = 8; o > 0; o >>= 1) p += __shfl_xor_sync(0xffffffffu, p, o);
    if (lane16 == 0) out[e] = p + bp2[0];
}

// ---------------- launch ----------------------------------------------------
extern "C" void kernel_launch(void* const* d_in, const int* in_sizes, int n_in,
                              void* d_out, int out_size)
{
    const float* x    = (const float*)d_in[0];
    const int*   src  = (const int*)d_in[1];
    const int*   dst  = (const int*)d_in[2];
    const int*   nsrc = (const int*)d_in[3];
    const int*   ndst = (const int*)d_in[4];
    const float* Ws1 = (const float*)d_in[5],  *Wn1 = (const float*)d_in[6],  *b1 = (const float*)d_in[7];
    const float* Ws2 = (const float*)d_in[8],  *Wn2 = (const float*)d_in[9],  *b2 = (const float*)d_in[10];
    const float* Ws3 = (const float*)d_in[11], *Wn3 = (const float*)d_in[12], *b3 = (const float*)d_in[13];
    const float* Wp1 = (const float*)d_in[14], *bp1 = (const float*)d_in[15];
    const float* Wp2 = (const float*)d_in[16], *bp2 = (const float*)d_in[17];
    float* out = (float*)d_out;

    __half *p_pa16, *p_pb16, *p_x, *p_m, *p_h1, *p_h2, *p_wh;
    float* p_bc;
    cudaGetSymbolAddress((void**)&p_pa16, g_pa16);
    cudaGetSymbolAddress((void**)&p_pb16, g_pb16);
    cudaGetSymbolAddress((void**)&p_x, g_x);
    cudaGetSymbolAddress((void**)&p_m, g_m);
    cudaGetSymbolAddress((void**)&p_h1, g_h1);
    cudaGetSymbolAddress((void**)&p_h2, g_h2);
    cudaGetSymbolAddress((void**)&p_wh, g_wh);
    cudaGetSymbolAddress((void**)&p_bc, g_bc);

    cudaFuncSetAttribute(k_gemm_tc, cudaFuncAttributeMaxDynamicSharedMemorySize,
                         GEMM_SMEM);

    // --- fused prologue: x-cvt + hist + weight prep (independent work) ---
    k_prep<<<CVT_BLOCKS + HIST_BLOCKS + WPREP_BLOCKS, 256>>>(
        x, p_x, dst, Ws1, Wn1, Ws2, Wn2, Ws3, Wn3, Wp1, b3, bp1);
    // --- CSR scan + place ---
    k_scan_fused<<<NB_SCAN, 1024>>>();
    k_place<<<(N_EDGES / 4 + 255) / 256, 256>>>(src, dst);

    const int aggBlocks  = (N_NODES * 16 + 255) / 256;
    const int gemmBlocks = (N_NODES + 127) / 128;

    // --- layer 1 ---
    k_agg<<<aggBlocks, 256>>>(p_x);
    k_gemm_tc<<<gemmBlocks, 256, GEMM_SMEM>>>(p_x, p_m, p_wh, b1,
                                              p_h1, nullptr, N_NODES, 256);
    // --- layer 2 ---
    k_agg<<<aggBlocks, 256>>>(p_h1);
    k_gemm_tc<<<gemmBlocks, 256, GEMM_SMEM>>>(p_h1, p_m, p_wh + 256 * D, b2,
                                              p_h2, nullptr, N_NODES, 256);
    // --- layer 3 + predictor (fused via composed weights; gridDim.y=2) ---
    k_agg<<<aggBlocks, 256>>>(p_h2);
    k_gemm_tc<<<dim3(gemmBlocks, 2), 256, GEMM_SMEM>>>(
                                              p_h2, p_m, p_wh + 512 * D, p_bc,
                                              p_pa16, p_pb16, N_NODES, 256);

    // --- edge scores (+ restores cnt/ready invariant) ---
    k_edge<<<(2 * N_EDGES * 16 + 255) / 256, 256>>>(src, dst, nsrc, ndst, Wp2, bp2, out);
}

// round 16
// speedup vs baseline: 1.0304x; 1.0304x over previous
#include <cuda_runtime.h>
#include <cuda_bf16.h>
#include <cuda_fp16.h>
#include <cstdint>

#define N_NODES 100000
#define N_EDGES 640000
#define D 128
#define NB_SCAN ((N_NODES + 1023) / 1024)    // 98

#define CVT_BLOCKS 12500                     // N_NODES*D/4 / 256
#define HIST_BLOCKS 625                      // N_EDGES / (256*4)
#define WPREP_BLOCKS 513

// ---------------- scratch (device globals: zero at module load) ------------
__device__ __align__(16) __half g_pa16[N_NODES * D];
__device__ __align__(16) __half g_pb16[N_NODES * D];
// node tensors: fp16 [N][128]
__device__ __align__(16) __half g_x[N_NODES * D];
__device__ __align__(16) __half g_m[N_NODES * D];
__device__ __align__(16) __half g_h1[N_NODES * D];
__device__ __align__(16) __half g_h2[N_NODES * D];
// packed weights [K][N] fp16:
// rows [Ws1|Wn1 (0-255) | Ws2|Wn2 (256-511) | comp_pa (512-767) | comp_pb (768-1023)]
__device__ __align__(16) __half g_wh[1024 * D];
__device__ float g_bc[2 * D];                // composed predictor biases
// CSR  (INVARIANT: g_cnt == 0 and g_ready == 0 at kernel_launch entry;
//       k_edge restores this at the end of every launch)
// g_csr holds BYTE offsets (src_node * 256) for direct addressing in k_agg.
__device__ int g_cnt[N_NODES];
__device__ int g_rowptr[N_NODES + 1];
__device__ int g_csr[N_EDGES];
__device__ int g_bsum[NB_SCAN];
__device__ int g_ready[NB_SCAN];

// ---------------- fused prologue: x-cvt + dst-hist + weight prep -----------
__global__ void k_prep(const float* __restrict__ x, __half* __restrict__ xo,
                       const int* __restrict__ dst,
                       const float* __restrict__ Ws1, const float* __restrict__ Wn1,
                       const float* __restrict__ Ws2, const float* __restrict__ Wn2,
                       const float* __restrict__ Ws3, const float* __restrict__ Wn3,
                       const float* __restrict__ Wp1, const float* __restrict__ b3,
                       const float* __restrict__ bp1) {
    int blk = blockIdx.x, tid = threadIdx.x;
    if (blk < CVT_BLOCKS) {                       // ---- x fp32 -> fp16
        int i = blk * 256 + tid;                  // < 3.2M exactly
        float4 v = ((const float4*)x)[i];
        __half2* p = (__half2*)&xo[i * 4];
        p[0] = __floats2half2_rn(v.x, v.y);
        p[1] = __floats2half2_rn(v.z, v.w);
    } else if (blk < CVT_BLOCKS + HIST_BLOCKS) {  // ---- degree histogram x4
        int e4 = (blk - CVT_BLOCKS) * 256 + tid;  // < 160000 exactly
        int4 d4 = ((const int4*)dst)[e4];
        atomicAdd(&g_cnt[d4.x], 1);
        atomicAdd(&g_cnt[d4.y], 1);
        atomicAdd(&g_cnt[d4.z], 1);
        atomicAdd(&g_cnt[d4.w], 1);
    } else {                                      // ---- weight prep
        int wb = blk - CVT_BLOCKS - HIST_BLOCKS;  // 0..512
        if (wb < 256) {                           // layer 1/2 weights
            int i = wb * 256 + tid;
            int row = i >> 7, col = i & 127;
            const float* s; int lr;
            if      (row < 128)  { s = Ws1; lr = row; }
            else if (row < 256)  { s = Wn1; lr = row - 128; }
            else if (row < 384)  { s = Ws2; lr = row - 256; }
            else                 { s = Wn2; lr = row - 384; }
            g_wh[i] = __float2half_rn(s[lr * D + col]);
        } else if (wb < 512) {                    // composed predictor weights
            __shared__ float xr[2][128];
            int idx = (wb - 256) * 2 + (tid >> 7);
            int p = idx >> 7, i = idx & 127;
            int sub = tid >> 7, n = tid & 127;
            const float* X = (p & 1) ? Wn3 : Ws3;
            const float* Y = Wp1 + ((p >> 1) ? 128 * D : 0);
            xr[sub][n] = X[i * D + n];
            __syncthreads();
            float s = 0.f;
            #pragma unroll 8
            for (int k = 0; k < 128; k++) s += xr[sub][k] * Y[k * D + n];
            int dstrow = ((p < 2) ? 512 : 768) + (p & 1) * 128 + i;
            g_wh[dstrow * D + n] = __float2half_rn(s);
        } else {                                  // composed biases
            int half = tid >> 7, n = tid & 127;
            float s = (half == 0) ? bp1[n] : 0.f;
            for (int j = 0; j < 128; j++) s += b3[j] * Wp1[(half * 128 + j) * D + n];
            g_bc[half * D + n] = s;
        }
    }
}

// fused scan: per-block scan + decoupled aggregate lookback + rowptr + cnt reset
__global__ void k_scan_fused() {
    __shared__ int sh[1024];
    __shared__ int red[32];
    int tid = threadIdx.x, blk = blockIdx.x;
    int i = blk * 1024 + tid;
    int v = (i < N_NODES) ? g_cnt[i] : 0;
    sh[tid] = v;
    __syncthreads();
    for (int o = 1; o < 1024; o <<= 1) {
        int t = (tid >= o) ? sh[tid - o] : 0;
        __syncthreads();
        sh[tid] += t;
        __syncthreads();
    }
    int total = sh[1023];
    if (tid == 0) {
        *(volatile int*)&g_bsum[blk] = total;
        __threadfence();
        *(volatile int*)&g_ready[blk] = 1;
    }
    int myv = 0;
    for (int j = tid; j < blk; j += 1024) {
        while (*(volatile int*)&g_ready[j] == 0) {}
        myv += *(volatile int*)&g_bsum[j];
    }
    #pragma unroll
    for (int o = 16; o > 0; o >>= 1) myv += __shfl_xor_sync(0xffffffffu, myv, o);
    if ((tid & 31) == 0) red[tid >> 5] = myv;
    __syncthreads();
    if (tid == 0) {
        int s = 0;
        #pragma unroll
        for (int w = 0; w < 32; w++) s += red[w];
        red[0] = s;
    }
    __syncthreads();
    int pref = red[0];
    if (i < N_NODES) {
        g_rowptr[i] = pref + sh[tid] - v;    // global exclusive
        g_cnt[i] = 0;                        // reset for k_place
    }
    if (blk == NB_SCAN - 1 && tid == 1023) g_rowptr[N_NODES] = pref + total;
}

// 4 edges per thread; csr stores BYTE offsets (src * 256)
__global__ void k_place(const int* __restrict__ src, const int* __restrict__ dst) {
    int e4 = blockIdx.x * blockDim.x + threadIdx.x;
    if (e4 >= N_EDGES / 4) return;
    int4 d4 = ((const int4*)dst)[e4];
    int4 s4 = ((const int4*)src)[e4];
    int p0 = g_rowptr[d4.x] + atomicAdd(&g_cnt[d4.x], 1);
    int p1 = g_rowptr[d4.y] + atomicAdd(&g_cnt[d4.y], 1);
    int p2 = g_rowptr[d4.z] + atomicAdd(&g_cnt[d4.z], 1);
    int p3 = g_rowptr[d4.w] + atomicAdd(&g_cnt[d4.w], 1);
    g_csr[p0] = s4.x << 8; g_csr[p1] = s4.y << 8;
    g_csr[p2] = s4.z << 8; g_csr[p3] = s4.w << 8;
}

// ---------------- mean aggregation: half-warp/node, 2-edge fp16 pre-add ----
// (round-14 loop shape: 32 regs / high occupancy; byte-offset addressing)
__global__ void k_agg(const __half* __restrict__ xin) {
    int g = blockIdx.x * blockDim.x + threadIdx.x;
    int node = g >> 4, lane16 = g & 15;
    if (node >= N_NODES) return;
    int beg = g_rowptr[node], end = g_rowptr[node + 1];
    const char* bp = (const char*)xin + lane16 * 16;
    float a0 = 0.f, a1 = 0.f, a2 = 0.f, a3 = 0.f;
    float a4 = 0.f, a5 = 0.f, a6 = 0.f, a7 = 0.f;
    int e = beg;
    for (; e + 1 < end; e += 2) {
        int o0 = g_csr[e], o1 = g_csr[e + 1];
        const uint4 v0 = *(const uint4*)(bp + o0);
        const uint4 v1 = *(const uint4*)(bp + o1);
        // pairwise fp16 add (one extra 2^-11 rounding per pair: negligible)
        __half2 t0 = __hadd2(*(__half2*)&v0.x, *(__half2*)&v1.x);
        __half2 t1 = __hadd2(*(__half2*)&v0.y, *(__half2*)&v1.y);
        __half2 t2 = __hadd2(*(__half2*)&v0.z, *(__half2*)&v1.z);
        __half2 t3 = __hadd2(*(__half2*)&v0.w, *(__half2*)&v1.w);
        float2 f;
        f = __half22float2(t0); a0 += f.x; a1 += f.y;
        f = __half22float2(t1); a2 += f.x; a3 += f.y;
        f = __half22float2(t2); a4 += f.x; a5 += f.y;
        f = __half22float2(t3); a6 += f.x; a7 += f.y;
    }
    if (e < end) {
        const uint4 v = *(const uint4*)(bp + g_csr[e]);
        float2 f;
        f = __half22float2(*(__half2*)&v.x); a0 += f.x; a1 += f.y;
        f = __half22float2(*(__half2*)&v.y); a2 += f.x; a3 += f.y;
        f = __half22float2(*(__half2*)&v.z); a4 += f.x; a5 += f.y;
        f = __half22float2(*(__half2*)&v.w); a6 += f.x; a7 += f.y;
    }
    int deg = end - beg;
    float inv = 1.0f / (float)(deg > 1 ? deg : 1);
    uint4 outv;
    *(__half2*)&outv.x = __floats2half2_rn(a0 * inv, a1 * inv);
    *(__half2*)&outv.y = __floats2half2_rn(a2 * inv, a3 * inv);
    *(__half2*)&outv.z = __floats2half2_rn(a4 * inv, a5 * inv);
    *(__half2*)&outv.w = __floats2half2_rn(a6 * inv, a7 * inv);
    *(uint4*)((char*)g_m + (size_t)node * 256 + lane16 * 16) = outv;
}

// ---------------- tensor-core GEMM (fp16, 1-term, 3-stage, 2 CTA/SM) -------
__device__ __forceinline__ void ldsm4(uint32_t& r0, uint32_t& r1, uint32_t& r2,
                                      uint32_t& r3, uint32_t addr) {
    asm volatile("ldmatrix.sync.aligned.m8n8.x4.shared.b16 {%0,%1,%2,%3}, [%4];"
                 : "=r"(r0), "=r"(r1), "=r"(r2), "=r"(r3) : "r"(addr));
}
__device__ __forceinline__ void ldsm4t(uint32_t& r0, uint32_t& r1, uint32_t& r2,
                                       uint32_t& r3, uint32_t addr) {
    asm volatile("ldmatrix.sync.aligned.m8n8.x4.trans.shared.b16 {%0,%1,%2,%3}, [%4];"
                 : "=r"(r0), "=r"(r1), "=r"(r2), "=r"(r3) : "r"(addr));
}
__device__ __forceinline__ void mma_fp16(float* c, const uint32_t* a, const uint32_t* b) {
    asm volatile(
        "mma.sync.aligned.m16n8k16.row.col.f32.f16.f16.f32 "
        "{%0,%1,%2,%3},{%4,%5,%6,%7},{%8,%9},{%0,%1,%2,%3};"
        : "+f"(c[0]), "+f"(c[1]), "+f"(c[2]), "+f"(c[3])
        : "r"(a[0]), "r"(a[1]), "r"(a[2]), "r"(a[3]), "r"(b[0]), "r"(b[1]));
}
__device__ __forceinline__ void cp16(uint32_t s, const void* g, bool p) {
    asm volatile("cp.async.cg.shared.global [%0], [%1], 16, %2;"
                 :: "r"(s), "l"(g), "r"(p ? 16 : 0));
}

#define A_STRIDE 80u
#define B_STRIDE 272u
#define A_BYTES (128u * A_STRIDE)            // 10240
#define B_BYTES (32u * B_STRIDE)             // 8704
#define STAGE (A_BYTES + B_BYTES)            // 18944
#define GEMM_SMEM (3 * STAGE)                // 56832 -> 2 CTAs/SM

// out[M,128] = (A1|A2)[M,K=256] @ W[K,128] + bias ; fp16.
// If pred (gridDim.y==2): y==1 selects W+256 rows, bias+128, out=outB.
__global__ __launch_bounds__(256, 2) void k_gemm_tc(
    const __half* __restrict__ A1, const __half* __restrict__ A2,
    const __half* __restrict__ Wh,
    const float* __restrict__ bias,
    __half* __restrict__ outA, __half* __restrict__ outB,
    int M, int K)
{
    extern __shared__ char smdyn[];
    uint32_t base = (uint32_t)__cvta_generic_to_shared(smdyn);

    __half* outp = outA;
    if (outB && blockIdx.y == 1) {
        Wh += 256 * D; bias += 128; outp = outB;
    }

    int tid = threadIdx.x;
    int wid = tid >> 5, lane = tid & 31;
    int warp_m = (wid >> 2) * 64;
    int warp_n = (wid & 3) * 32;
    int m0 = blockIdx.x * 128;
    int nch = K / 32;

    float c[4][4][4];
    #pragma unroll
    for (int i = 0; i < 4; i++)
        #pragma unroll
        for (int j = 0; j < 4; j++)
            #pragma unroll
            for (int q = 0; q < 4; q++) c[i][j][q] = 0.f;

    auto load_chunk = [&](int ch) {
        uint32_t st = base + (uint32_t)(ch % 3) * STAGE;
        int kb = ch * 32;
        const __half* A = (kb < 128) ? A1 : A2;
        int ac = kb & 127;
        #pragma unroll
        for (int l = tid; l < 512; l += 256) {      // A: 128 rows x 4 segs(16B)
            int r = l >> 2, seg = l & 3;
            uint32_t so = (uint32_t)r * A_STRIDE + (uint32_t)seg * 16u;
            bool p = (m0 + r) < M;
            int rr = p ? (m0 + r) : 0;
            cp16(st + so, A + (size_t)rr * D + ac + seg * 8, p);
        }
        #pragma unroll
        for (int l = tid; l < 512; l += 256) {      // B: 32 rows x 16 segs
            int r = l >> 4, seg = l & 15;
            uint32_t so = (uint32_t)r * B_STRIDE + (uint32_t)seg * 16u;
            cp16(st + A_BYTES + so, Wh + (size_t)(kb + r) * D + seg * 8, true);
        }
        asm volatile("cp.async.commit_group;" ::: "memory");
    };

    load_chunk(0);
    load_chunk(1);

    int lr = (lane & 7) + 8 * ((lane >> 3) & 1);
    int lc = 8 * (lane >> 4);

    for (int ch = 0; ch < nch; ch++) {
        if (ch + 1 < nch) {
            asm volatile("cp.async.wait_group 1;" ::: "memory");
        } else {
            asm volatile("cp.async.wait_group 0;" ::: "memory");
        }
        __syncthreads();     // single barrier: orders stage reuse + visibility
        if (ch + 2 < nch) load_chunk(ch + 2);

        uint32_t st  = base + (uint32_t)(ch % 3) * STAGE;
        uint32_t a_b = st;
        uint32_t b_b = st + A_BYTES;

        #pragma unroll
        for (int ks = 0; ks < 2; ks++) {
            int k0 = ks * 16;
            uint32_t a[4][4];
            #pragma unroll
            for (int mi = 0; mi < 4; mi++) {
                uint32_t ro = (uint32_t)(warp_m + mi * 16 + lr) * A_STRIDE
                            + (uint32_t)(k0 + lc) * 2u;
                ldsm4(a[mi][0], a[mi][1], a[mi][2], a[mi][3], a_b + ro);
            }
            uint32_t b[4][2];
            #pragma unroll
            for (int njp = 0; njp < 2; njp++) {
                uint32_t ro = (uint32_t)(k0 + lr) * B_STRIDE
                            + (uint32_t)(warp_n + njp * 16 + lc) * 2u;
                uint32_t r0, r1, r2, r3;
                ldsm4t(r0, r1, r2, r3, b_b + ro);
                b[2 * njp][0] = r0;     b[2 * njp][1] = r1;
                b[2 * njp + 1][0] = r2; b[2 * njp + 1][1] = r3;
            }
            #pragma unroll
            for (int mi = 0; mi < 4; mi++)
                #pragma unroll
                for (int nj = 0; nj < 4; nj++)
                    mma_fp16(c[mi][nj], a[mi], b[nj]);
        }
    }

    // epilogue: fp16 output
    #pragma unroll
    for (int mi = 0; mi < 4; mi++) {
        #pragma unroll
        for (int nj = 0; nj < 4; nj++) {
            int row0 = m0 + warp_m + mi * 16 + (lane >> 2);
            int col  = warp_n + nj * 8 + (lane & 3) * 2;
            float b0 = bias ? bias[col] : 0.f;
            float b1 = bias ? bias[col + 1] : 0.f;
            #pragma unroll
            for (int h = 0; h < 2; h++) {
                int row = row0 + 8 * h;
                if (row < M) {
                    float v0 = c[mi][nj][2 * h]     + b0;
                    float v1 = c[mi][nj][2 * h + 1] + b1;
                    *(__half2*)&outp[(size_t)row * D + col] =
                        __floats2half2_rn(v0, v1);
                }
            }
        }
    }
}

// ---------------- edge scoring + state reset (16 lanes/edge) ----------------
__global__ void k_edge(const int* __restrict__ s1, const int* __restrict__ d1,
                       const int* __restrict__ s2, const int* __restrict__ d2,
                       const float* __restrict__ Wp2, const float* __restrict__ bp2,
                       float* __restrict__ out)
{
    int g = blockIdx.x * blockDim.x + threadIdx.x;
    // restore launch-entry invariant (g_cnt == 0, g_ready == 0)
    if (g < N_NODES) g_cnt[g] = 0;
    if (g < NB_SCAN) g_ready[g] = 0;
    int e = g >> 4, lane16 = g & 15;
    if (e >= 2 * N_EDGES) return;
    int ss, dd;
    if (e < N_EDGES) { ss = s1[e]; dd = d1[e]; }
    else             { ss = s2[e - N_EDGES]; dd = d2[e - N_EDGES]; }

    const char* pab = (const char*)g_pa16 + ((size_t)ss << 8) + lane16 * 16;
    const char* pbb = (const char*)g_pb16 + ((size_t)dd << 8) + lane16 * 16;
    uint4 av = *(const uint4*)pab;
    uint4 bv = *(const uint4*)pbb;
    float4 w0 = *(const float4*)&Wp2[lane16 * 8];
    float4 w1 = *(const float4*)&Wp2[lane16 * 8 + 4];

    float2 a0 = __half22float2(*(__half2*)&av.x);
    float2 a1 = __half22float2(*(__half2*)&av.y);
    float2 a2 = __half22float2(*(__half2*)&av.z);
    float2 a3 = __half22float2(*(__half2*)&av.w);
    float2 b0 = __half22float2(*(__half2*)&bv.x);
    float2 b1 = __half22float2(*(__half2*)&bv.y);
    float2 b2 = __half22float2(*(__half2*)&bv.z);
    float2 b3 = __half22float2(*(__half2*)&bv.w);

    float p = fmaxf(a0.x + b0.x, 0.f) * w0.x
            + fmaxf(a0.y + b0.y, 0.f) * w0.y
            + fmaxf(a1.x + b1.x, 0.f) * w0.z
            + fmaxf(a1.y + b1.y, 0.f) * w0.w
            + fmaxf(a2.x + b2.x, 0.f) * w1.x
            + fmaxf(a2.y + b2.y, 0.f) * w1.y
            + fmaxf(a3.x + b3.x, 0.f) * w1.z
            + fmaxf(a3.y + b3.y, 0.f) * w1.w;
    #pragma unroll
    for (int o = 8; o > 0; o >>= 1) p += __shfl_xor_sync(0xffffffffu, p, o);
    if (lane16 == 0) out[e] = p + bp2[0];
}

// ---------------- launch ----------------------------------------------------
extern "C" void kernel_launch(void* const* d_in, const int* in_sizes, int n_in,
                              void* d_out, int out_size)
{
    const float* x    = (const float*)d_in[0];
    const int*   src  = (const int*)d_in[1];
    const int*   dst  = (const int*)d_in[2];
    const int*   nsrc = (const int*)d_in[3];
    const int*   ndst = (const int*)d_in[4];
    const float* Ws1 = (const float*)d_in[5],  *Wn1 = (const float*)d_in[6],  *b1 = (const float*)d_in[7];
    const float* Ws2 = (const float*)d_in[8],  *Wn2 = (const float*)d_in[9],  *b2 = (const float*)d_in[10];
    const float* Ws3 = (const float*)d_in[11], *Wn3 = (const float*)d_in[12], *b3 = (const float*)d_in[13];
    const float* Wp1 = (const float*)d_in[14], *bp1 = (const float*)d_in[15];
    const float* Wp2 = (const float*)d_in[16], *bp2 = (const float*)d_in[17];
    float* out = (float*)d_out;

    __half *p_pa16, *p_pb16, *p_x, *p_m, *p_h1, *p_h2, *p_wh;
    float* p_bc;
    cudaGetSymbolAddress((void**)&p_pa16, g_pa16);
    cudaGetSymbolAddress((void**)&p_pb16, g_pb16);
    cudaGetSymbolAddress((void**)&p_x, g_x);
    cudaGetSymbolAddress((void**)&p_m, g_m);
    cudaGetSymbolAddress((void**)&p_h1, g_h1);
    cudaGetSymbolAddress((void**)&p_h2, g_h2);
    cudaGetSymbolAddress((void**)&p_wh, g_wh);
    cudaGetSymbolAddress((void**)&p_bc, g_bc);

    cudaFuncSetAttribute(k_gemm_tc, cudaFuncAttributeMaxDynamicSharedMemorySize,
                         GEMM_SMEM);

    // --- fused prologue: x-cvt + hist + weight prep (independent work) ---
    k_prep<<<CVT_BLOCKS + HIST_BLOCKS + WPREP_BLOCKS, 256>>>(
        x, p_x, dst, Ws1, Wn1, Ws2, Wn2, Ws3, Wn3, Wp1, b3, bp1);
    // --- CSR scan + place ---
    k_scan_fused<<<NB_SCAN, 1024>>>();
    k_place<<<(N_EDGES / 4 + 255) / 256, 256>>>(src, dst);

    const int aggBlocks  = (N_NODES * 16 + 255) / 256;
    const int gemmBlocks = (N_NODES + 127) / 128;

    // --- layer 1 ---
    k_agg<<<aggBlocks, 256>>>(p_x);
    k_gemm_tc<<<gemmBlocks, 256, GEMM_SMEM>>>(p_x, p_m, p_wh, b1,
                                              p_h1, nullptr, N_NODES, 256);
    // --- layer 2 ---
    k_agg<<<aggBlocks, 256>>>(p_h1);
    k_gemm_tc<<<gemmBlocks, 256, GEMM_SMEM>>>(p_h1, p_m, p_wh + 256 * D, b2,
                                              p_h2, nullptr, N_NODES, 256);
    // --- layer 3 + predictor (fused via composed weights; gridDim.y=2) ---
    k_agg<<<aggBlocks, 256>>>(p_h2);
    k_gemm_tc<<<dim3(gemmBlocks, 2), 256, GEMM_SMEM>>>(
                                              p_h2, p_m, p_wh + 512 * D, p_bc,
                                              p_pa16, p_pb16, N_NODES, 256);

    // --- edge scores (+ restores cnt/ready invariant) ---
    k_edge<<<(2 * N_EDGES * 16 + 255) / 256, 256>>>(src, dst, nsrc, ndst, Wp2, bp2, out);
}

// round 17
// speedup vs baseline: 1.0368x; 1.0063x over previous
#include <cuda_runtime.h>
#include <cuda_bf16.h>
#include <cuda_fp16.h>
#include <cstdint>

#define N_NODES 100000
#define N_EDGES 640000
#define D 128
#define NB_SCAN ((N_NODES + 1023) / 1024)    // 98

#define CVT_BLOCKS 12500                     // N_NODES*D/4 / 256
#define HIST_BLOCKS 625                      // N_EDGES / (256*4)
#define WPREP_BLOCKS 513

// ---------------- scratch (device globals: zero at module load) ------------
__device__ __align__(16) __half g_pa16[N_NODES * D];
__device__ __align__(16) __half g_pb16[N_NODES * D];
// node tensors: fp16 [N][128]
__device__ __align__(16) __half g_x[N_NODES * D];
__device__ __align__(16) __half g_m[N_NODES * D];
__device__ __align__(16) __half g_h1[N_NODES * D];
__device__ __align__(16) __half g_h2[N_NODES * D];
// packed weights [K][N] fp16:
// rows [Ws1|Wn1 (0-255) | Ws2|Wn2 (256-511) | comp_pa (512-767) | comp_pb (768-1023)]
__device__ __align__(16) __half g_wh[1024 * D];
__device__ float g_bc[2 * D];                // composed predictor biases
// CSR  (INVARIANT: g_cnt == 0 and g_ready == 0 at kernel_launch entry;
//       k_edge restores this at the end of every launch)
__device__ int g_cnt[N_NODES];
__device__ int g_rowptr[N_NODES + 1];
__device__ int g_csr[N_EDGES];
__device__ int g_bsum[NB_SCAN];
__device__ int g_ready[NB_SCAN];

// ---------------- fused prologue: x-cvt + dst-hist + weight prep -----------
__global__ void k_prep(const float* __restrict__ x, __half* __restrict__ xo,
                       const int* __restrict__ dst,
                       const float* __restrict__ Ws1, const float* __restrict__ Wn1,
                       const float* __restrict__ Ws2, const float* __restrict__ Wn2,
                       const float* __restrict__ Ws3, const float* __restrict__ Wn3,
                       const float* __restrict__ Wp1, const float* __restrict__ b3,
                       const float* __restrict__ bp1) {
    int blk = blockIdx.x, tid = threadIdx.x;
    if (blk < CVT_BLOCKS) {                       // ---- x fp32 -> fp16
        int i = blk * 256 + tid;                  // < 3.2M exactly
        float4 v = ((const float4*)x)[i];
        __half2* p = (__half2*)&xo[i * 4];
        p[0] = __floats2half2_rn(v.x, v.y);
        p[1] = __floats2half2_rn(v.z, v.w);
    } else if (blk < CVT_BLOCKS + HIST_BLOCKS) {  // ---- degree histogram x4
        int e4 = (blk - CVT_BLOCKS) * 256 + tid;  // < 160000 exactly
        int4 d4 = ((const int4*)dst)[e4];
        atomicAdd(&g_cnt[d4.x], 1);
        atomicAdd(&g_cnt[d4.y], 1);
        atomicAdd(&g_cnt[d4.z], 1);
        atomicAdd(&g_cnt[d4.w], 1);
    } else {                                      // ---- weight prep
        int wb = blk - CVT_BLOCKS - HIST_BLOCKS;  // 0..512
        if (wb < 256) {                           // layer 1/2 weights
            int i = wb * 256 + tid;
            int row = i >> 7, col = i & 127;
            const float* s; int lr;
            if      (row < 128)  { s = Ws1; lr = row; }
            else if (row < 256)  { s = Wn1; lr = row - 128; }
            else if (row < 384)  { s = Ws2; lr = row - 256; }
            else                 { s = Wn2; lr = row - 384; }
            g_wh[i] = __float2half_rn(s[lr * D + col]);
        } else if (wb < 512) {                    // composed predictor weights
            __shared__ float xr[2][128];
            int idx = (wb - 256) * 2 + (tid >> 7);
            int p = idx >> 7, i = idx & 127;
            int sub = tid >> 7, n = tid & 127;
            const float* X = (p & 1) ? Wn3 : Ws3;
            const float* Y = Wp1 + ((p >> 1) ? 128 * D : 0);
            xr[sub][n] = X[i * D + n];
            __syncthreads();
            float s = 0.f;
            #pragma unroll 8
            for (int k = 0; k < 128; k++) s += xr[sub][k] * Y[k * D + n];
            int dstrow = ((p < 2) ? 512 : 768) + (p & 1) * 128 + i;
            g_wh[dstrow * D + n] = __float2half_rn(s);
        } else {                                  // composed biases
            int half = tid >> 7, n = tid & 127;
            float s = (half == 0) ? bp1[n] : 0.f;
            for (int j = 0; j < 128; j++) s += b3[j] * Wp1[(half * 128 + j) * D + n];
            g_bc[half * D + n] = s;
        }
    }
}

// fused scan: per-block scan + decoupled aggregate lookback + rowptr + cnt reset
__global__ void k_scan_fused() {
    __shared__ int sh[1024];
    __shared__ int red[32];
    int tid = threadIdx.x, blk = blockIdx.x;
    int i = blk * 1024 + tid;
    int v = (i < N_NODES) ? g_cnt[i] : 0;
    sh[tid] = v;
    __syncthreads();
    for (int o = 1; o < 1024; o <<= 1) {
        int t = (tid >= o) ? sh[tid - o] : 0;
        __syncthreads();
        sh[tid] += t;
        __syncthreads();
    }
    int total = sh[1023];
    if (tid == 0) {
        *(volatile int*)&g_bsum[blk] = total;
        __threadfence();
        *(volatile int*)&g_ready[blk] = 1;
    }
    int myv = 0;
    for (int j = tid; j < blk; j += 1024) {
        while (*(volatile int*)&g_ready[j] == 0) {}
        myv += *(volatile int*)&g_bsum[j];
    }
    #pragma unroll
    for (int o = 16; o > 0; o >>= 1) myv += __shfl_xor_sync(0xffffffffu, myv, o);
    if ((tid & 31) == 0) red[tid >> 5] = myv;
    __syncthreads();
    if (tid == 0) {
        int s = 0;
        #pragma unroll
        for (int w = 0; w < 32; w++) s += red[w];
        red[0] = s;
    }
    __syncthreads();
    int pref = red[0];
    if (i < N_NODES) {
        g_rowptr[i] = pref + sh[tid] - v;    // global exclusive
        g_cnt[i] = 0;                        // reset for k_place
    }
    if (blk == NB_SCAN - 1 && tid == 1023) g_rowptr[N_NODES] = pref + total;
}

// 4 edges per thread (MLP); csr stores plain node indices (round-14 form)
__global__ void k_place(const int* __restrict__ src, const int* __restrict__ dst) {
    int e4 = blockIdx.x * blockDim.x + threadIdx.x;
    if (e4 >= N_EDGES / 4) return;
    int4 d4 = ((const int4*)dst)[e4];
    int4 s4 = ((const int4*)src)[e4];
    int p0 = g_rowptr[d4.x] + atomicAdd(&g_cnt[d4.x], 1);
    int p1 = g_rowptr[d4.y] + atomicAdd(&g_cnt[d4.y], 1);
    int p2 = g_rowptr[d4.z] + atomicAdd(&g_cnt[d4.z], 1);
    int p3 = g_rowptr[d4.w] + atomicAdd(&g_cnt[d4.w], 1);
    g_csr[p0] = s4.x; g_csr[p1] = s4.y; g_csr[p2] = s4.z; g_csr[p3] = s4.w;
}

// ---------------- mean aggregation: round-14 winner, reg-capped ------------
// half-warp/node, 16 B loads, 2-edge fp16 pairwise pre-add; <=32 regs forced.
__global__ __launch_bounds__(256, 8) void k_agg(const __half* __restrict__ xin) {
    int g = blockIdx.x * blockDim.x + threadIdx.x;
    int node = g >> 4, lane16 = g & 15;
    if (node >= N_NODES) return;
    int beg = g_rowptr[node], end = g_rowptr[node + 1];
    float a0 = 0.f, a1 = 0.f, a2 = 0.f, a3 = 0.f;
    float a4 = 0.f, a5 = 0.f, a6 = 0.f, a7 = 0.f;
    int e = beg;
    for (; e + 1 < end; e += 2) {
        int s0 = g_csr[e], s1 = g_csr[e + 1];
        const uint4 v0 = *(const uint4*)&xin[(size_t)s0 * D + lane16 * 8];
        const uint4 v1 = *(const uint4*)&xin[(size_t)s1 * D + lane16 * 8];
        // pairwise fp16 add (one extra 2^-11 rounding per pair: negligible)
        __half2 t0 = __hadd2(*(__half2*)&v0.x, *(__half2*)&v1.x);
        __half2 t1 = __hadd2(*(__half2*)&v0.y, *(__half2*)&v1.y);
        __half2 t2 = __hadd2(*(__half2*)&v0.z, *(__half2*)&v1.z);
        __half2 t3 = __hadd2(*(__half2*)&v0.w, *(__half2*)&v1.w);
        float2 f;
        f = __half22float2(t0); a0 += f.x; a1 += f.y;
        f = __half22float2(t1); a2 += f.x; a3 += f.y;
        f = __half22float2(t2); a4 += f.x; a5 += f.y;
        f = __half22float2(t3); a6 += f.x; a7 += f.y;
    }
    if (e < end) {
        const uint4 v = *(const uint4*)&xin[(size_t)g_csr[e] * D + lane16 * 8];
        float2 f;
        f = __half22float2(*(__half2*)&v.x); a0 += f.x; a1 += f.y;
        f = __half22float2(*(__half2*)&v.y); a2 += f.x; a3 += f.y;
        f = __half22float2(*(__half2*)&v.z); a4 += f.x; a5 += f.y;
        f = __half22float2(*(__half2*)&v.w); a6 += f.x; a7 += f.y;
    }
    int deg = end - beg;
    float inv = 1.0f / (float)(deg > 1 ? deg : 1);
    uint4 outv;
    *(__half2*)&outv.x = __floats2half2_rn(a0 * inv, a1 * inv);
    *(__half2*)&outv.y = __floats2half2_rn(a2 * inv, a3 * inv);
    *(__half2*)&outv.z = __floats2half2_rn(a4 * inv, a5 * inv);
    *(__half2*)&outv.w = __floats2half2_rn(a6 * inv, a7 * inv);
    *(uint4*)&g_m[(size_t)node * D + lane16 * 8] = outv;
}

// ---------------- tensor-core GEMM (fp16, 1-term, 3-stage, 2 CTA/SM) -------
__device__ __forceinline__ void ldsm4(uint32_t& r0, uint32_t& r1, uint32_t& r2,
                                      uint32_t& r3, uint32_t addr) {
    asm volatile("ldmatrix.sync.aligned.m8n8.x4.shared.b16 {%0,%1,%2,%3}, [%4];"
                 : "=r"(r0), "=r"(r1), "=r"(r2), "=r"(r3) : "r"(addr));
}
__device__ __forceinline__ void ldsm4t(uint32_t& r0, uint32_t& r1, uint32_t& r2,
                                       uint32_t& r3, uint32_t addr) {
    asm volatile("ldmatrix.sync.aligned.m8n8.x4.trans.shared.b16 {%0,%1,%2,%3}, [%4];"
                 : "=r"(r0), "=r"(r1), "=r"(r2), "=r"(r3) : "r"(addr));
}
__device__ __forceinline__ void mma_fp16(float* c, const uint32_t* a, const uint32_t* b) {
    asm volatile(
        "mma.sync.aligned.m16n8k16.row.col.f32.f16.f16.f32 "
        "{%0,%1,%2,%3},{%4,%5,%6,%7},{%8,%9},{%0,%1,%2,%3};"
        : "+f"(c[0]), "+f"(c[1]), "+f"(c[2]), "+f"(c[3])
        : "r"(a[0]), "r"(a[1]), "r"(a[2]), "r"(a[3]), "r"(b[0]), "r"(b[1]));
}
__device__ __forceinline__ void cp16(uint32_t s, const void* g, bool p) {
    asm volatile("cp.async.cg.shared.global [%0], [%1], 16, %2;"
                 :: "r"(s), "l"(g), "r"(p ? 16 : 0));
}

#define A_STRIDE 80u
#define B_STRIDE 272u
#define A_BYTES (128u * A_STRIDE)            // 10240
#define B_BYTES (32u * B_STRIDE)             // 8704
#define STAGE (A_BYTES + B_BYTES)            // 18944
#define GEMM_SMEM (3 * STAGE)                // 56832 -> 2 CTAs/SM

// out[M,128] = (A1|A2)[M,K=256] @ W[K,128] + bias ; fp16.
// If pred (gridDim.y==2): y==1 selects W+256 rows, bias+128, out=outB.
__global__ __launch_bounds__(256, 2) void k_gemm_tc(
    const __half* __restrict__ A1, const __half* __restrict__ A2,
    const __half* __restrict__ Wh,
    const float* __restrict__ bias,
    __half* __restrict__ outA, __half* __restrict__ outB,
    int M, int K)
{
    extern __shared__ char smdyn[];
    uint32_t base = (uint32_t)__cvta_generic_to_shared(smdyn);

    __half* outp = outA;
    if (outB && blockIdx.y == 1) {
        Wh += 256 * D; bias += 128; outp = outB;
    }

    int tid = threadIdx.x;
    int wid = tid >> 5, lane = tid & 31;
    int warp_m = (wid >> 2) * 64;
    int warp_n = (wid & 3) * 32;
    int m0 = blockIdx.x * 128;
    int nch = K / 32;

    float c[4][4][4];
    #pragma unroll
    for (int i = 0; i < 4; i++)
        #pragma unroll
        for (int j = 0; j < 4; j++)
            #pragma unroll
            for (int q = 0; q < 4; q++) c[i][j][q] = 0.f;

    auto load_chunk = [&](int ch) {
        uint32_t st = base + (uint32_t)(ch % 3) * STAGE;
        int kb = ch * 32;
        const __half* A = (kb < 128) ? A1 : A2;
        int ac = kb & 127;
        #pragma unroll
        for (int l = tid; l < 512; l += 256) {      // A: 128 rows x 4 segs(16B)
            int r = l >> 2, seg = l & 3;
            uint32_t so = (uint32_t)r * A_STRIDE + (uint32_t)seg * 16u;
            bool p = (m0 + r) < M;
            int rr = p ? (m0 + r) : 0;
            cp16(st + so, A + (size_t)rr * D + ac + seg * 8, p);
        }
        #pragma unroll
        for (int l = tid; l < 512; l += 256) {      // B: 32 rows x 16 segs
            int r = l >> 4, seg = l & 15;
            uint32_t so = (uint32_t)r * B_STRIDE + (uint32_t)seg * 16u;
            cp16(st + A_BYTES + so, Wh + (size_t)(kb + r) * D + seg * 8, true);
        }
        asm volatile("cp.async.commit_group;" ::: "memory");
    };

    load_chunk(0);
    load_chunk(1);

    int lr = (lane & 7) + 8 * ((lane >> 3) & 1);
    int lc = 8 * (lane >> 4);

    for (int ch = 0; ch < nch; ch++) {
        if (ch + 1 < nch) {
            asm volatile("cp.async.wait_group 1;" ::: "memory");
        } else {
            asm volatile("cp.async.wait_group 0;" ::: "memory");
        }
        __syncthreads();     // single barrier: orders stage reuse + visibility
        if (ch + 2 < nch) load_chunk(ch + 2);

        uint32_t st  = base + (uint32_t)(ch % 3) * STAGE;
        uint32_t a_b = st;
        uint32_t b_b = st + A_BYTES;

        #pragma unroll
        for (int ks = 0; ks < 2; ks++) {
            int k0 = ks * 16;
            uint32_t a[4][4];
            #pragma unroll
            for (int mi = 0; mi < 4; mi++) {
                uint32_t ro = (uint32_t)(warp_m + mi * 16 + lr) * A_STRIDE
                            + (uint32_t)(k0 + lc) * 2u;
                ldsm4(a[mi][0], a[mi][1], a[mi][2], a[mi][3], a_b + ro);
            }
            uint32_t b[4][2];
            #pragma unroll
            for (int njp = 0; njp < 2; njp++) {
                uint32_t ro = (uint32_t)(k0 + lr) * B_STRIDE
                            + (uint32_t)(warp_n + njp * 16 + lc) * 2u;
                uint32_t r0, r1, r2, r3;
                ldsm4t(r0, r1, r2, r3, b_b + ro);
                b[2 * njp][0] = r0;     b[2 * njp][1] = r1;
                b[2 * njp + 1][0] = r2; b[2 * njp + 1][1] = r3;
            }
            #pragma unroll
            for (int mi = 0; mi < 4; mi++)
                #pragma unroll
                for (int nj = 0; nj < 4; nj++)
                    mma_fp16(c[mi][nj], a[mi], b[nj]);
        }
    }

    // epilogue: fp16 output
    #pragma unroll
    for (int mi = 0; mi < 4; mi++) {
        #pragma unroll
        for (int nj = 0; nj < 4; nj++) {
            int row0 = m0 + warp_m + mi * 16 + (lane >> 2);
            int col  = warp_n + nj * 8 + (lane & 3) * 2;
            float b0 = bias ? bias[col] : 0.f;
            float b1 = bias ? bias[col + 1] : 0.f;
            #pragma unroll
            for (int h = 0; h < 2; h++) {
                int row = row0 + 8 * h;
                if (row < M) {
                    float v0 = c[mi][nj][2 * h]     + b0;
                    float v1 = c[mi][nj][2 * h + 1] + b1;
                    *(__half2*)&outp[(size_t)row * D + col] =
                        __floats2half2_rn(v0, v1);
                }
            }
        }
    }
}

// ---------------- edge scoring + state reset (16 lanes/edge) ----------------
__global__ void k_edge(const int* __restrict__ s1, const int* __restrict__ d1,
                       const int* __restrict__ s2, const int* __restrict__ d2,
                       const float* __restrict__ Wp2, const float* __restrict__ bp2,
                       float* __restrict__ out)
{
    int g = blockIdx.x * blockDim.x + threadIdx.x;
    // restore launch-entry invariant (g_cnt == 0, g_ready == 0)
    if (g < N_NODES) g_cnt[g] = 0;
    if (g < NB_SCAN) g_ready[g] = 0;
    int e = g >> 4, lane16 = g & 15;
    if (e >= 2 * N_EDGES) return;
    int ss, dd;
    if (e < N_EDGES) { ss = s1[e]; dd = d1[e]; }
    else             { ss = s2[e - N_EDGES]; dd = d2[e - N_EDGES]; }

    const char* pab = (const char*)g_pa16 + ((size_t)ss << 8) + lane16 * 16;
    const char* pbb = (const char*)g_pb16 + ((size_t)dd << 8) + lane16 * 16;
    uint4 av = *(const uint4*)pab;
    uint4 bv = *(const uint4*)pbb;
    float4 w0 = *(const float4*)&Wp2[lane16 * 8];
    float4 w1 = *(const float4*)&Wp2[lane16 * 8 + 4];

    float2 a0 = __half22float2(*(__half2*)&av.x);
    float2 a1 = __half22float2(*(__half2*)&av.y);
    float2 a2 = __half22float2(*(__half2*)&av.z);
    float2 a3 = __half22float2(*(__half2*)&av.w);
    float2 b0 = __half22float2(*(__half2*)&bv.x);
    float2 b1 = __half22float2(*(__half2*)&bv.y);
    float2 b2 = __half22float2(*(__half2*)&bv.z);
    float2 b3 = __half22float2(*(__half2*)&bv.w);

    float p = fmaxf(a0.x + b0.x, 0.f) * w0.x
            + fmaxf(a0.y + b0.y, 0.f) * w0.y
            + fmaxf(a1.x + b1.x, 0.f) * w0.z
            + fmaxf(a1.y + b1.y, 0.f) * w0.w
            + fmaxf(a2.x + b2.x, 0.f) * w1.x
            + fmaxf(a2.y + b2.y, 0.f) * w1.y
            + fmaxf(a3.x + b3.x, 0.f) * w1.z
            + fmaxf(a3.y + b3.y, 0.f) * w1.w;
    #pragma unroll
    for (int o = 8; o > 0; o >>= 1) p += __shfl_xor_sync(0xffffffffu, p, o);
    if (lane16 == 0) out[e] = p + bp2[0];
}

// ---------------- launch ----------------------------------------------------
extern "C" void kernel_launch(void* const* d_in, const int* in_sizes, int n_in,
                              void* d_out, int out_size)
{
    const float* x    = (const float*)d_in[0];
    const int*   src  = (const int*)d_in[1];
    const int*   dst  = (const int*)d_in[2];
    const int*   nsrc = (const int*)d_in[3];
    const int*   ndst = (const int*)d_in[4];
    const float* Ws1 = (const float*)d_in[5],  *Wn1 = (const float*)d_in[6],  *b1 = (const float*)d_in[7];
    const float* Ws2 = (const float*)d_in[8],  *Wn2 = (const float*)d_in[9],  *b2 = (const float*)d_in[10];
    const float* Ws3 = (const float*)d_in[11], *Wn3 = (const float*)d_in[12], *b3 = (const float*)d_in[13];
    const float* Wp1 = (const float*)d_in[14], *bp1 = (const float*)d_in[15];
    const float* Wp2 = (const float*)d_in[16], *bp2 = (const float*)d_in[17];
    float* out = (float*)d_out;

    __half *p_pa16, *p_pb16, *p_x, *p_m, *p_h1, *p_h2, *p_wh;
    float* p_bc;
    cudaGetSymbolAddress((void**)&p_pa16, g_pa16);
    cudaGetSymbolAddress((void**)&p_pb16, g_pb16);
    cudaGetSymbolAddress((void**)&p_x, g_x);
    cudaGetSymbolAddress((void**)&p_m, g_m);
    cudaGetSymbolAddress((void**)&p_h1, g_h1);
    cudaGetSymbolAddress((void**)&p_h2, g_h2);
    cudaGetSymbolAddress((void**)&p_wh, g_wh);
    cudaGetSymbolAddress((void**)&p_bc, g_bc);

    cudaFuncSetAttribute(k_gemm_tc, cudaFuncAttributeMaxDynamicSharedMemorySize,
                         GEMM_SMEM);

    // --- fused prologue: x-cvt + hist + weight prep (independent work) ---
    k_prep<<<CVT_BLOCKS + HIST_BLOCKS + WPREP_BLOCKS, 256>>>(
        x, p_x, dst, Ws1, Wn1, Ws2, Wn2, Ws3, Wn3, Wp1, b3, bp1);
    // --- CSR scan + place ---
    k_scan_fused<<<NB_SCAN, 1024>>>();
    k_place<<<(N_EDGES / 4 + 255) / 256, 256>>>(src, dst);

    const int aggBlocks  = (N_NODES * 16 + 255) / 256;
    const int gemmBlocks = (N_NODES + 127) / 128;

    // --- layer 1 ---
    k_agg<<<aggBlocks, 256>>>(p_x);
    k_gemm_tc<<<gemmBlocks, 256, GEMM_SMEM>>>(p_x, p_m, p_wh, b1,
                                              p_h1, nullptr, N_NODES, 256);
    // --- layer 2 ---
    k_agg<<<aggBlocks, 256>>>(p_h1);
    k_gemm_tc<<<gemmBlocks, 256, GEMM_SMEM>>>(p_h1, p_m, p_wh + 256 * D, b2,
                                              p_h2, nullptr, N_NODES, 256);
    // --- layer 3 + predictor (fused via composed weights; gridDim.y=2) ---
    k_agg<<<aggBlocks, 256>>>(p_h2);
    k_gemm_tc<<<dim3(gemmBlocks, 2), 256, GEMM_SMEM>>>(
                                              p_h2, p_m, p_wh + 512 * D, p_bc,
                                              p_pa16, p_pb16, N_NODES, 256);

    // --- edge scores (+ restores cnt/ready invariant) ---
    k_edge<<<(2 * N_EDGES * 16 + 255) / 256, 256>>>(src, dst, nsrc, ndst, Wp2, bp2, out);
}